// round 3
// baseline (speedup 1.0000x reference)
#include <cuda_runtime.h>
#include <math.h>

#define CC    128
#define NHEAD 4
#define DHD   32
#define LMAXC 64
#define GENES 4096
#define SN    136        // normal row stride (floats), 16B-aligned rows
#define SKT   69         // K-transposed stride (odd -> conflict-free reads)
#define BUF_N  (64 * SN)         // 8704 floats
#define BUF_KT (128 * SKT)       // 8832 floats
#define SMEM_FLOATS (3 * BUF_N + BUF_KT)
#define SMEM_BYTES  (SMEM_FLOATS * 4)

__device__ __forceinline__ float warp_sum(float v) {
#pragma unroll
    for (int o = 16; o; o >>= 1) v += __shfl_xor_sync(0xffffffffu, v, o);
    return v;
}
__device__ __forceinline__ float warp_max(float v) {
#pragma unroll
    for (int o = 16; o; o >>= 1) v = fmaxf(v, __shfl_xor_sync(0xffffffffu, v, o));
    return v;
}

// X[rows,128] (smem, stride SN) @ W[128,128] (global, row-major) + bias -> Y
// Warp w owns rows {w, w+8, ...}; lane owns 4 output cols. X loads are warp-broadcast.
// TRANS: write Y transposed with stride SKT (for K^T). RELU: fused relu.
template <bool TRANS, bool RELU>
__device__ void mm64(const float* X, const float* __restrict__ W,
                     const float* __restrict__ bias, float* Y,
                     int rows, int w, int lane)
{
    int nr = (rows > w) ? (((rows - 1 - w) >> 3) + 1) : 0;
    if (nr == 0) return;
    int c0 = lane * 4;
    float acc[8][4];
#pragma unroll
    for (int i = 0; i < 8; i++) { acc[i][0] = 0.f; acc[i][1] = 0.f; acc[i][2] = 0.f; acc[i][3] = 0.f; }

#pragma unroll 2
    for (int kk = 0; kk < CC; kk += 4) {
        float4 w0 = *(const float4*)(W + (kk + 0) * CC + c0);
        float4 w1 = *(const float4*)(W + (kk + 1) * CC + c0);
        float4 w2 = *(const float4*)(W + (kk + 2) * CC + c0);
        float4 w3 = *(const float4*)(W + (kk + 3) * CC + c0);
#pragma unroll
        for (int i = 0; i < 8; i++) {
            if (i < nr) {   // nr is warp-uniform -> cheap branch, real FMA savings
                float4 xv = *(const float4*)(X + (w + 8 * i) * SN + kk);
                acc[i][0] = fmaf(xv.x, w0.x, acc[i][0]);
                acc[i][1] = fmaf(xv.x, w0.y, acc[i][1]);
                acc[i][2] = fmaf(xv.x, w0.z, acc[i][2]);
                acc[i][3] = fmaf(xv.x, w0.w, acc[i][3]);
                acc[i][0] = fmaf(xv.y, w1.x, acc[i][0]);
                acc[i][1] = fmaf(xv.y, w1.y, acc[i][1]);
                acc[i][2] = fmaf(xv.y, w1.z, acc[i][2]);
                acc[i][3] = fmaf(xv.y, w1.w, acc[i][3]);
                acc[i][0] = fmaf(xv.z, w2.x, acc[i][0]);
                acc[i][1] = fmaf(xv.z, w2.y, acc[i][1]);
                acc[i][2] = fmaf(xv.z, w2.z, acc[i][2]);
                acc[i][3] = fmaf(xv.z, w2.w, acc[i][3]);
                acc[i][0] = fmaf(xv.w, w3.x, acc[i][0]);
                acc[i][1] = fmaf(xv.w, w3.y, acc[i][1]);
                acc[i][2] = fmaf(xv.w, w3.z, acc[i][2]);
                acc[i][3] = fmaf(xv.w, w3.w, acc[i][3]);
            }
        }
    }
    float4 bv = *(const float4*)(bias + c0);
#pragma unroll
    for (int i = 0; i < 8; i++) {
        if (i < nr) {
            int r = w + 8 * i;
            float o0 = acc[i][0] + bv.x, o1 = acc[i][1] + bv.y;
            float o2 = acc[i][2] + bv.z, o3 = acc[i][3] + bv.w;
            if (RELU) { o0 = fmaxf(o0, 0.f); o1 = fmaxf(o1, 0.f); o2 = fmaxf(o2, 0.f); o3 = fmaxf(o3, 0.f); }
            if (!TRANS) {
                *(float4*)(Y + r * SN + c0) = make_float4(o0, o1, o2, o3);
            } else {
                Y[(c0 + 0) * SKT + r] = o0;
                Y[(c0 + 1) * SKT + r] = o1;
                Y[(c0 + 2) * SKT + r] = o2;
                Y[(c0 + 3) * SKT + r] = o3;
            }
        }
    }
}

// 1-row matmul: y[c] = sum_k X[k]*W[k][c] + b[c], thread-per-column (tid<128)
template <bool RELU>
__device__ void mm1(const float* __restrict__ X, const float* __restrict__ W,
                    const float* __restrict__ bias, float* Y, int tid)
{
    if (tid < CC) {
        float acc = bias[tid];
#pragma unroll 8
        for (int k = 0; k < CC; k++) acc = fmaf(X[k], W[k * CC + tid], acc);
        if (RELU) acc = fmaxf(acc, 0.f);
        Y[tid] = acc;
    }
}

// Multi-head attention. Q/O share a buffer (stride SN); Kt (stride SKT); V (stride SN).
// Task = (query row, head); one warp per task; lane owns kv rows {lane, lane+32} for
// scores and output column d=lane for AV. Writes O over Q (slice-disjoint, safe).
__device__ void attn_mh(float* QO, const float* Kt, const float* V,
                        int Lq, int len, int kvr, int w, int lane)
{
    const float scale = 0.17677669529663687f;   // 1/sqrt(32)
    int ntask = Lq * NHEAD;
    for (int t = w; t < ntask; t += 8) {
        int r = t >> 2, h = t & 3;
        int base = h * DHD;
        float s0 = 0.f, s1 = 0.f;
#pragma unroll
        for (int d = 0; d < DHD; d++) {
            float qd = QO[r * SN + base + d];                 // broadcast
            s0 = fmaf(qd, Kt[(base + d) * SKT + lane], s0);   // conflict-free (odd stride)
            s1 = fmaf(qd, Kt[(base + d) * SKT + lane + 32], s1);
        }
        s0 = (lane < len)      ? s0 * scale : -1e30f;
        s1 = (lane + 32 < len) ? s1 * scale : -1e30f;
        float m = warp_max(fmaxf(s0, s1));
        float p0 = __expf(s0 - m), p1 = __expf(s1 - m);
        float inv = 1.f / warp_sum(p0 + p1);
        float a0 = p0 * inv, a1 = p1 * inv;

        float acc = 0.f;
        int k0 = kvr < 32 ? kvr : 32;
        for (int k = 0; k < k0; k++)
            acc = fmaf(__shfl_sync(0xffffffffu, a0, k), V[k * SN + base + lane], acc);
        for (int k = 32; k < kvr; k++)
            acc = fmaf(__shfl_sync(0xffffffffu, a1, k - 32), V[k * SN + base + lane], acc);
        QO[r * SN + base + lane] = acc;
    }
}

// out[r] = LN( (r<qmasklen ? A[r] : 0) + Res[r] ) * g + b   (row-wise over 128)
__device__ void lnres(const float* A, const float* Res, float* Out,
                      int rows, int qmasklen,
                      const float* __restrict__ g, const float* __restrict__ b,
                      int w, int lane)
{
    for (int r = w; r < rows; r += 8) {
        float4 a = (r < qmasklen) ? *(const float4*)(A + r * SN + lane * 4)
                                  : make_float4(0.f, 0.f, 0.f, 0.f);
        float4 s = *(const float4*)(Res + r * SN + lane * 4);
        float t0 = a.x + s.x, t1 = a.y + s.y, t2 = a.z + s.z, t3 = a.w + s.w;
        float sum = warp_sum(t0 + t1 + t2 + t3);
        float sq  = warp_sum(t0 * t0 + t1 * t1 + t2 * t2 + t3 * t3);
        float mean = sum * (1.f / 128.f);
        float var  = sq * (1.f / 128.f) - mean * mean;
        float rstd = rsqrtf(var + 1e-5f);
        float4 gv = *(const float4*)(g + lane * 4);
        float4 bv = *(const float4*)(b + lane * 4);
        float4 o;
        o.x = (t0 - mean) * rstd * gv.x + bv.x;
        o.y = (t1 - mean) * rstd * gv.y + bv.y;
        o.z = (t2 - mean) * rstd * gv.z + bv.z;
        o.w = (t3 - mean) * rstd * gv.w + bv.w;
        *(float4*)(Out + r * SN + lane * 4) = o;
    }
}

__global__ __launch_bounds__(256, 1)
void gene_mapper_kernel(const float* __restrict__ rf,
                        const float* __restrict__ Wq, const float* __restrict__ Wk,
                        const float* __restrict__ Wv, const float* __restrict__ Wo,
                        const float* __restrict__ bq, const float* __restrict__ bk,
                        const float* __restrict__ bv, const float* __restrict__ bo,
                        const float* __restrict__ Wlin, const float* __restrict__ blin,
                        const float* __restrict__ g1, const float* __restrict__ b1,
                        const float* __restrict__ g2, const float* __restrict__ b2,
                        const float* __restrict__ seed,
                        const int* __restrict__ rxn_idx,
                        const int* __restrict__ gene_idx,
                        float* __restrict__ out, int E)
{
    extern __shared__ float sm[];
    float* Sst = sm;                 // state / residual  [64][SN]
    float* SA  = sm + BUF_N;         // Q then attn-O     [64][SN]
    float* SB  = SA + BUF_N;         // K^T [128][SKT]  or normal [64][SN]
    float* SC  = SB + BUF_KT;        // V / FF            [64][SN]
    __shared__ int s_start, s_len;

    int g    = blockIdx.x;
    int tid  = threadIdx.x;
    int w    = tid >> 5;
    int lane = tid & 31;

    if (tid == 0) {
        int lo = 0, hi = E;
        while (lo < hi) { int m = (lo + hi) >> 1; if (gene_idx[m] < g) lo = m + 1; else hi = m; }
        int st = lo; hi = E;
        while (lo < hi) { int m = (lo + hi) >> 1; if (gene_idx[m] <= g) lo = m + 1; else hi = m; }
        s_start = st;
        int c = lo - st;
        s_len = c < LMAXC ? c : LMAXC;
    }
    __syncthreads();
    int start = s_start, len = s_len;
    int lenr = (len + 7) & ~7;                 // rows actually computed
    if (lenr > LMAXC) lenr = LMAXC;

    // gather reaction rows -> Sst; zero pad rows [len, lenr)
    for (int r = w; r < lenr; r += 8) {
        if (r < len) {
            int rx = rxn_idx[start + r];
            ((float4*)(Sst + r * SN))[lane] = ((const float4*)(rf + (size_t)rx * CC))[lane];
        } else {
            ((float4*)(Sst + r * SN))[lane] = make_float4(0.f, 0.f, 0.f, 0.f);
        }
    }
    __syncthreads();

    // ---- encoder SAB blocks 0,1 ----
    for (int blk = 0; blk < 2; blk++) {
        const float* wq = Wq + blk * CC * CC;  const float* wk = Wk + blk * CC * CC;
        const float* wv = Wv + blk * CC * CC;  const float* wo = Wo + blk * CC * CC;
        const float* wl = Wlin + blk * CC * CC;
        mm64<false, false>(Sst, wq, bq + blk * CC, SA, lenr, w, lane);
        mm64<true,  false>(Sst, wk, bk + blk * CC, SB, lenr, w, lane);
        mm64<false, false>(Sst, wv, bv + blk * CC, SC, lenr, w, lane);
        __syncthreads();
        attn_mh(SA, SB, SC, lenr, len, lenr, w, lane);
        __syncthreads();
        mm64<false, false>(SA, wo, bo + blk * CC, SB, lenr, w, lane);   // attn proj -> SB
        __syncthreads();
        lnres(SB, Sst, Sst, lenr, len, g1 + blk * CC, b1 + blk * CC, w, lane);
        __syncthreads();
        mm64<false, true>(Sst, wl, blin + blk * CC, SC, lenr, w, lane); // FF with relu
        __syncthreads();
        lnres(SC, Sst, Sst, lenr, lenr, g2 + blk * CC, b2 + blk * CC, w, lane);
        __syncthreads();
    }

    // ---- PMA (block 2): q = seed (1 row), kv = state ----
    {
        const int blk = 2;
        mm1<false>(seed, Wq + blk * CC * CC, bq + blk * CC, SA, tid);       // Q row0
        mm64<true,  false>(Sst, Wk + blk * CC * CC, bk + blk * CC, SB, lenr, w, lane);
        mm64<false, false>(Sst, Wv + blk * CC * CC, bv + blk * CC, SC, lenr, w, lane);
        __syncthreads();
        attn_mh(SA, SB, SC, 1, len, lenr, w, lane);
        __syncthreads();
        mm1<false>(SA, Wo + blk * CC * CC, bo + blk * CC, SB, tid);         // O proj row0
        __syncthreads();
        lnres(SB, seed, Sst, 1, 1, g1 + blk * CC, b1 + blk * CC, w, lane);  // residual = seed
        __syncthreads();
        mm1<true>(Sst, Wlin + blk * CC * CC, blin + blk * CC, SC, tid);
        __syncthreads();
        lnres(SC, Sst, Sst, 1, 1, g2 + blk * CC, b2 + blk * CC, w, lane);
        __syncthreads();
    }

    // ---- decoder SAB (block 3), Lq=Lk=1 => softmax == 1 => attn = V ----
    {
        const int blk = 3;
        mm1<false>(Sst, Wv + blk * CC * CC, bv + blk * CC, SA, tid);        // v
        __syncthreads();
        mm1<false>(SA, Wo + blk * CC * CC, bo + blk * CC, SB, tid);         // v @ Wo + bo
        __syncthreads();
        lnres(SB, Sst, Sst, 1, 1, g1 + blk * CC, b1 + blk * CC, w, lane);
        __syncthreads();
        mm1<true>(Sst, Wlin + blk * CC * CC, blin + blk * CC, SC, tid);
        __syncthreads();
        lnres(SC, Sst, Sst, 1, 1, g2 + blk * CC, b2 + blk * CC, w, lane);
        __syncthreads();

        if (tid < CC) {
            float v = Sst[tid];
            if (v != v) v = 0.f;                               // nan_to_num
            v = fminf(fmaxf(v, -3.402823466e38f), 3.402823466e38f);
            out[(size_t)g * CC + tid] = v;
        }
    }
}

extern "C" void kernel_launch(void* const* d_in, const int* in_sizes, int n_in,
                              void* d_out, int out_size)
{
    const float* rf   = (const float*)d_in[0];
    const float* Wq   = (const float*)d_in[1];
    const float* Wk   = (const float*)d_in[2];
    const float* Wv   = (const float*)d_in[3];
    const float* Wo   = (const float*)d_in[4];
    const float* bq   = (const float*)d_in[5];
    const float* bk   = (const float*)d_in[6];
    const float* bv   = (const float*)d_in[7];
    const float* bo   = (const float*)d_in[8];
    const float* Wlin = (const float*)d_in[9];
    const float* blin = (const float*)d_in[10];
    const float* g1   = (const float*)d_in[11];
    const float* b1   = (const float*)d_in[12];
    const float* g2   = (const float*)d_in[13];
    const float* b2   = (const float*)d_in[14];
    const float* seed = (const float*)d_in[15];
    const int*   rxn  = (const int*)d_in[16];
    const int*   gidx = (const int*)d_in[17];
    int E = in_sizes[16];

    cudaFuncSetAttribute(gene_mapper_kernel,
                         cudaFuncAttributeMaxDynamicSharedMemorySize, SMEM_BYTES);
    gene_mapper_kernel<<<GENES, 256, SMEM_BYTES>>>(
        rf, Wq, Wk, Wv, Wo, bq, bk, bv, bo, Wlin, blin,
        g1, b1, g2, b2, seed, rxn, gidx, (float*)d_out, E);
}

// round 5
// speedup vs baseline: 2.4150x; 2.4150x over previous
#include <cuda_runtime.h>
#include <math.h>

#define CC    128
#define GENES 4096

// ---- main (len<=32) kernel geometry ----
#define SR32  132                 // row stride (floats)
#define SKT32 33                  // K^T stride
#define B32   (32 * SR32)         // 4224 floats
#define KT32  (128 * SKT32)       // 4224 floats
#define SM32_FLOATS (3 * B32 + KT32 + 256)
#define SM32_BYTES  (SM32_FLOATS * 4)      // ~68.6 KB -> 3 CTAs/SM

// ---- long (len>32) kernel geometry ----
#define SR64  136
#define SKT64 69
#define B64   (64 * SR64)
#define KT64  (128 * SKT64)
#define SM64_FLOATS (3 * B64 + KT64 + 256)
#define SM64_BYTES  (SM64_FLOATS * 4)

__device__ int g_starts[GENES + 1];
__device__ int g_longcount;
__device__ int g_longlist[GENES];

__device__ __forceinline__ float warp_sum(float v) {
#pragma unroll
    for (int o = 16; o; o >>= 1) v += __shfl_xor_sync(0xffffffffu, v, o);
    return v;
}
__device__ __forceinline__ float warp_max(float v) {
#pragma unroll
    for (int o = 16; o; o >>= 1) v = fmaxf(v, __shfl_xor_sync(0xffffffffu, v, o));
    return v;
}

// ============================================================================
// bounds kernel: mark segment starts (gene_idx sorted, every gene nonempty)
// ============================================================================
__global__ void seg_bounds_kernel(const int* __restrict__ gene_idx, int E)
{
    int e = blockIdx.x * 256 + threadIdx.x;
    if (e == 0) { g_starts[GENES] = E; g_longcount = 0; }
    if (e < E) {
        int gi = gene_idx[e];
        if (e == 0 || gene_idx[e - 1] != gi) g_starts[gi] = e;
    }
}

// ============================================================================
// mm32: X[rows<=32,128] @ W + b -> Y.  8 warps = 4 row-groups x 2 col-halves.
// Each warp loads only HALF of W (its 64 columns). Lane owns 2 cols (float2).
// ============================================================================
template <bool TRANS, bool RELU>
__device__ void mm32(const float* X, const float* __restrict__ W,
                     const float* __restrict__ bias, float* Y,
                     int rows, int w, int lane)
{
    int rg = w >> 1;                    // 0..3, rows rg, rg+4, ...
    int ch = w & 1;                     // col half
    int c0 = ch * 64 + lane * 2;
    int nr = (rows > rg) ? (((rows - 1 - rg) >> 2) + 1) : 0;   // <= 8
    if (nr == 0) return;
    float acc[8][2];
#pragma unroll
    for (int i = 0; i < 8; i++) { acc[i][0] = 0.f; acc[i][1] = 0.f; }

#pragma unroll 2
    for (int kk = 0; kk < CC; kk += 4) {
        float2 w0 = *(const float2*)(W + (kk + 0) * CC + c0);
        float2 w1 = *(const float2*)(W + (kk + 1) * CC + c0);
        float2 w2 = *(const float2*)(W + (kk + 2) * CC + c0);
        float2 w3 = *(const float2*)(W + (kk + 3) * CC + c0);
#pragma unroll
        for (int i = 0; i < 8; i++) {
            if (i < nr) {
                float4 xv = *(const float4*)(X + (rg + 4 * i) * SR32 + kk);
                acc[i][0] = fmaf(xv.x, w0.x, acc[i][0]);
                acc[i][1] = fmaf(xv.x, w0.y, acc[i][1]);
                acc[i][0] = fmaf(xv.y, w1.x, acc[i][0]);
                acc[i][1] = fmaf(xv.y, w1.y, acc[i][1]);
                acc[i][0] = fmaf(xv.z, w2.x, acc[i][0]);
                acc[i][1] = fmaf(xv.z, w2.y, acc[i][1]);
                acc[i][0] = fmaf(xv.w, w3.x, acc[i][0]);
                acc[i][1] = fmaf(xv.w, w3.y, acc[i][1]);
            }
        }
    }
    float2 bv = *(const float2*)(bias + c0);
#pragma unroll
    for (int i = 0; i < 8; i++) {
        if (i < nr) {
            int r = rg + 4 * i;
            float o0 = acc[i][0] + bv.x, o1 = acc[i][1] + bv.y;
            if (RELU) { o0 = fmaxf(o0, 0.f); o1 = fmaxf(o1, 0.f); }
            if (!TRANS) {
                *(float2*)(Y + r * SR32 + c0) = make_float2(o0, o1);
            } else {
                Y[(c0 + 0) * SKT32 + r] = o0;
                Y[(c0 + 1) * SKT32 + r] = o1;
            }
        }
    }
}

// ============================================================================
// mm64row: original row-split matmul for the long (64-row) kernel
// ============================================================================
template <bool TRANS, bool RELU>
__device__ void mm64row(const float* X, const float* __restrict__ W,
                        const float* __restrict__ bias, float* Y,
                        int rows, int w, int lane)
{
    int nr = (rows > w) ? (((rows - 1 - w) >> 3) + 1) : 0;
    if (nr == 0) return;
    int c0 = lane * 4;
    float acc[8][4];
#pragma unroll
    for (int i = 0; i < 8; i++) { acc[i][0]=0.f; acc[i][1]=0.f; acc[i][2]=0.f; acc[i][3]=0.f; }

#pragma unroll 2
    for (int kk = 0; kk < CC; kk += 4) {
        float4 w0 = *(const float4*)(W + (kk + 0) * CC + c0);
        float4 w1 = *(const float4*)(W + (kk + 1) * CC + c0);
        float4 w2 = *(const float4*)(W + (kk + 2) * CC + c0);
        float4 w3 = *(const float4*)(W + (kk + 3) * CC + c0);
#pragma unroll
        for (int i = 0; i < 8; i++) {
            if (i < nr) {
                float4 xv = *(const float4*)(X + (w + 8 * i) * SR64 + kk);
                acc[i][0]=fmaf(xv.x,w0.x,acc[i][0]); acc[i][1]=fmaf(xv.x,w0.y,acc[i][1]);
                acc[i][2]=fmaf(xv.x,w0.z,acc[i][2]); acc[i][3]=fmaf(xv.x,w0.w,acc[i][3]);
                acc[i][0]=fmaf(xv.y,w1.x,acc[i][0]); acc[i][1]=fmaf(xv.y,w1.y,acc[i][1]);
                acc[i][2]=fmaf(xv.y,w1.z,acc[i][2]); acc[i][3]=fmaf(xv.y,w1.w,acc[i][3]);
                acc[i][0]=fmaf(xv.z,w2.x,acc[i][0]); acc[i][1]=fmaf(xv.z,w2.y,acc[i][1]);
                acc[i][2]=fmaf(xv.z,w2.z,acc[i][2]); acc[i][3]=fmaf(xv.z,w2.w,acc[i][3]);
                acc[i][0]=fmaf(xv.w,w3.x,acc[i][0]); acc[i][1]=fmaf(xv.w,w3.y,acc[i][1]);
                acc[i][2]=fmaf(xv.w,w3.z,acc[i][2]); acc[i][3]=fmaf(xv.w,w3.w,acc[i][3]);
            }
        }
    }
    float4 bv = *(const float4*)(bias + c0);
#pragma unroll
    for (int i = 0; i < 8; i++) {
        if (i < nr) {
            int r = w + 8 * i;
            float o0=acc[i][0]+bv.x, o1=acc[i][1]+bv.y, o2=acc[i][2]+bv.z, o3=acc[i][3]+bv.w;
            if (RELU) { o0=fmaxf(o0,0.f); o1=fmaxf(o1,0.f); o2=fmaxf(o2,0.f); o3=fmaxf(o3,0.f); }
            if (!TRANS) {
                *(float4*)(Y + r * SR64 + c0) = make_float4(o0, o1, o2, o3);
            } else {
                Y[(c0+0)*SKT64 + r]=o0; Y[(c0+1)*SKT64 + r]=o1;
                Y[(c0+2)*SKT64 + r]=o2; Y[(c0+3)*SKT64 + r]=o3;
            }
        }
    }
}

// ============================================================================
// mm1 split over k (2 halves across 256 threads) + finalize
// ============================================================================
__device__ void mm1_part(const float* __restrict__ X, const float* __restrict__ W,
                         float* scratch, int tid)
{
    int col = tid & 127;
    int h   = tid >> 7;                 // 0/1
    const float* Wp = W + (h * 64) * CC + col;
    const float* Xp = X + h * 64;
    float acc = 0.f;
#pragma unroll 8
    for (int k = 0; k < 64; k++) acc = fmaf(Xp[k], Wp[k * CC], acc);
    scratch[tid] = acc;
}
template <bool RELU>
__device__ void mm1_fin(const float* scratch, const float* __restrict__ bias,
                        float* Y, int tid)
{
    if (tid < CC) {
        float v = scratch[tid] + scratch[tid + 128] + bias[tid];
        if (RELU) v = fmaxf(v, 0.f);
        Y[tid] = v;
    }
}

// ============================================================================
// attention (kv <= 32): one warp per (query row, head), lane = kv index
// ============================================================================
template <int SROW, int SKTV>
__device__ void attn32(float* QO, const float* Kt, const float* V,
                       int Lq, int len, int kvr, int w, int lane)
{
    const float scale = 0.17677669529663687f;   // 1/sqrt(32)
    int ntask = Lq * 4;
    for (int t = w; t < ntask; t += 8) {
        int r = t >> 2, base = (t & 3) * 32;
        float s = 0.f;
#pragma unroll
        for (int d = 0; d < 32; d++)
            s = fmaf(QO[r * SROW + base + d], Kt[(base + d) * SKTV + lane], s);
        s = (lane < len) ? s * scale : -1e30f;
        float m = warp_max(s);
        float p = __expf(s - m);
        float inv = 1.f / warp_sum(p);
        float a = p * inv;
        float acc = 0.f;
        for (int k = 0; k < kvr; k++)
            acc = fmaf(__shfl_sync(0xffffffffu, a, k), V[k * SROW + base + lane], acc);
        QO[r * SROW + base + lane] = acc;
    }
}

// attention (kv <= 64) for the long kernel
__device__ void attn64(float* QO, const float* Kt, const float* V,
                       int Lq, int len, int kvr, int w, int lane)
{
    const float scale = 0.17677669529663687f;
    int ntask = Lq * 4;
    for (int t = w; t < ntask; t += 8) {
        int r = t >> 2, base = (t & 3) * 32;
        float s0 = 0.f, s1 = 0.f;
#pragma unroll
        for (int d = 0; d < 32; d++) {
            float qd = QO[r * SR64 + base + d];
            s0 = fmaf(qd, Kt[(base + d) * SKT64 + lane], s0);
            s1 = fmaf(qd, Kt[(base + d) * SKT64 + lane + 32], s1);
        }
        s0 = (lane < len)      ? s0 * scale : -1e30f;
        s1 = (lane + 32 < len) ? s1 * scale : -1e30f;
        float m = warp_max(fmaxf(s0, s1));
        float p0 = __expf(s0 - m), p1 = __expf(s1 - m);
        float inv = 1.f / warp_sum(p0 + p1);
        float a0 = p0 * inv, a1 = p1 * inv;
        float acc = 0.f;
        int k0 = kvr < 32 ? kvr : 32;
        for (int k = 0; k < k0; k++)
            acc = fmaf(__shfl_sync(0xffffffffu, a0, k), V[k * SR64 + base + lane], acc);
        for (int k = 32; k < kvr; k++)
            acc = fmaf(__shfl_sync(0xffffffffu, a1, k - 32), V[k * SR64 + base + lane], acc);
        QO[r * SR64 + base + lane] = acc;
    }
}

// ============================================================================
// LN(residual + masked A) row-wise over 128
// ============================================================================
template <int SROW>
__device__ void lnres(const float* A, const float* Res, float* Out,
                      int rows, int qmasklen,
                      const float* __restrict__ g, const float* __restrict__ b,
                      int w, int lane)
{
    for (int r = w; r < rows; r += 8) {
        float4 a = (r < qmasklen) ? *(const float4*)(A + r * SROW + lane * 4)
                                  : make_float4(0.f, 0.f, 0.f, 0.f);
        float4 s = *(const float4*)(Res + r * SROW + lane * 4);
        float t0 = a.x + s.x, t1 = a.y + s.y, t2 = a.z + s.z, t3 = a.w + s.w;
        float sum = warp_sum(t0 + t1 + t2 + t3);
        float sq  = warp_sum(t0*t0 + t1*t1 + t2*t2 + t3*t3);
        float mean = sum * (1.f / 128.f);
        float var  = sq * (1.f / 128.f) - mean * mean;
        float rstd = rsqrtf(var + 1e-5f);
        float4 gv = *(const float4*)(g + lane * 4);
        float4 bv = *(const float4*)(b + lane * 4);
        float4 o;
        o.x = (t0 - mean) * rstd * gv.x + bv.x;
        o.y = (t1 - mean) * rstd * gv.y + bv.y;
        o.z = (t2 - mean) * rstd * gv.z + bv.z;
        o.w = (t3 - mean) * rstd * gv.w + bv.w;
        *(float4*)(Out + r * SROW + lane * 4) = o;
    }
}

// ============================================================================
// MAIN kernel: genes with len <= 32 (3 CTAs/SM)
// ============================================================================
__global__ __launch_bounds__(256, 3)
void gene_main32(const float* __restrict__ rf,
                 const float* __restrict__ Wq, const float* __restrict__ Wk,
                 const float* __restrict__ Wv, const float* __restrict__ Wo,
                 const float* __restrict__ bq, const float* __restrict__ bk,
                 const float* __restrict__ bv, const float* __restrict__ bo,
                 const float* __restrict__ Wlin, const float* __restrict__ blin,
                 const float* __restrict__ g1, const float* __restrict__ b1,
                 const float* __restrict__ g2, const float* __restrict__ b2,
                 const float* __restrict__ seed,
                 const int* __restrict__ rxn_idx,
                 float* __restrict__ out)
{
    extern __shared__ float sm[];
    float* Sst = sm;                    // state        [32][SR32]
    float* SA  = sm + B32;              // Q / attn-O   [32][SR32]
    float* SB  = SA + B32;              // K^T [128][SKT32] OR normal [32][SR32]
    float* SC  = SB + KT32;             // V / FF       [32][SR32]
    float* SCR = SC + B32;              // mm1 scratch  [256]

    int g    = blockIdx.x;
    int tid  = threadIdx.x;
    int w    = tid >> 5;
    int lane = tid & 31;

    int start = g_starts[g];
    int len   = g_starts[g + 1] - start;
    if (len > 32) {                     // defer to long kernel
        if (tid == 0) { int p = atomicAdd(&g_longcount, 1); g_longlist[p] = g; }
        return;
    }
    int lenr = (len + 7) & ~7;          // 8..32

    // gather
    for (int r = w; r < lenr; r += 8) {
        if (r < len) {
            int rx = rxn_idx[start + r];
            ((float4*)(Sst + r * SR32))[lane] = ((const float4*)(rf + (size_t)rx * CC))[lane];
        } else {
            ((float4*)(Sst + r * SR32))[lane] = make_float4(0.f, 0.f, 0.f, 0.f);
        }
    }
    __syncthreads();

    // encoder SABs
    for (int blk = 0; blk < 2; blk++) {
        const float* wq = Wq + blk * CC * CC;  const float* wk = Wk + blk * CC * CC;
        const float* wv = Wv + blk * CC * CC;  const float* wo = Wo + blk * CC * CC;
        const float* wl = Wlin + blk * CC * CC;
        mm32<false, false>(Sst, wq, bq + blk * CC, SA, lenr, w, lane);
        mm32<true,  false>(Sst, wk, bk + blk * CC, SB, lenr, w, lane);
        mm32<false, false>(Sst, wv, bv + blk * CC, SC, lenr, w, lane);
        __syncthreads();
        attn32<SR32, SKT32>(SA, SB, SC, lenr, len, lenr, w, lane);
        __syncthreads();
        mm32<false, false>(SA, wo, bo + blk * CC, SB, lenr, w, lane);
        __syncthreads();
        lnres<SR32>(SB, Sst, Sst, lenr, len, g1 + blk * CC, b1 + blk * CC, w, lane);
        __syncthreads();
        mm32<false, true>(Sst, wl, blin + blk * CC, SC, lenr, w, lane);
        __syncthreads();
        lnres<SR32>(SC, Sst, Sst, lenr, lenr, g2 + blk * CC, b2 + blk * CC, w, lane);
        __syncthreads();
    }

    // PMA (block 2)
    {
        const int blk = 2;
        mm1_part(seed, Wq + blk * CC * CC, SCR, tid);
        mm32<true,  false>(Sst, Wk + blk * CC * CC, bk + blk * CC, SB, lenr, w, lane);
        mm32<false, false>(Sst, Wv + blk * CC * CC, bv + blk * CC, SC, lenr, w, lane);
        __syncthreads();
        mm1_fin<false>(SCR, bq + blk * CC, SA, tid);    // Q row0
        __syncthreads();
        attn32<SR32, SKT32>(SA, SB, SC, 1, len, lenr, w, lane);
        __syncthreads();
        mm1_part(SA, Wo + blk * CC * CC, SCR, tid);
        __syncthreads();
        mm1_fin<false>(SCR, bo + blk * CC, SB, tid);
        __syncthreads();
        lnres<SR32>(SB, seed, Sst, 1, 1, g1 + blk * CC, b1 + blk * CC, w, lane);
        __syncthreads();
        mm1_part(Sst, Wlin + blk * CC * CC, SCR, tid);
        __syncthreads();
        mm1_fin<true>(SCR, blin + blk * CC, SC, tid);
        __syncthreads();
        lnres<SR32>(SC, Sst, Sst, 1, 1, g2 + blk * CC, b2 + blk * CC, w, lane);
        __syncthreads();
    }

    // decoder SAB (block 3): Lq=Lk=1 -> attn = V
    {
        const int blk = 3;
        mm1_part(Sst, Wv + blk * CC * CC, SCR, tid);
        __syncthreads();
        mm1_fin<false>(SCR, bv + blk * CC, SA, tid);
        __syncthreads();
        mm1_part(SA, Wo + blk * CC * CC, SCR, tid);
        __syncthreads();
        mm1_fin<false>(SCR, bo + blk * CC, SB, tid);
        __syncthreads();
        lnres<SR32>(SB, Sst, Sst, 1, 1, g1 + blk * CC, b1 + blk * CC, w, lane);
        __syncthreads();
        mm1_part(Sst, Wlin + blk * CC * CC, SCR, tid);
        __syncthreads();
        mm1_fin<true>(SCR, blin + blk * CC, SC, tid);
        __syncthreads();
        lnres<SR32>(SC, Sst, Sst, 1, 1, g2 + blk * CC, b2 + blk * CC, w, lane);
        __syncthreads();

        if (tid < CC) {
            float v = Sst[tid];
            if (v != v) v = 0.f;
            v = fminf(fmaxf(v, -3.402823466e38f), 3.402823466e38f);
            out[(size_t)g * CC + tid] = v;
        }
    }
}

// ============================================================================
// LONG kernel: genes with len > 32 (rare; persistent over atomic list)
// ============================================================================
__global__ __launch_bounds__(256, 1)
void gene_long64(const float* __restrict__ rf,
                 const float* __restrict__ Wq, const float* __restrict__ Wk,
                 const float* __restrict__ Wv, const float* __restrict__ Wo,
                 const float* __restrict__ bq, const float* __restrict__ bk,
                 const float* __restrict__ bv, const float* __restrict__ bo,
                 const float* __restrict__ Wlin, const float* __restrict__ blin,
                 const float* __restrict__ g1, const float* __restrict__ b1,
                 const float* __restrict__ g2, const float* __restrict__ b2,
                 const float* __restrict__ seed,
                 const int* __restrict__ rxn_idx,
                 float* __restrict__ out)
{
    extern __shared__ float sm[];
    float* Sst = sm;                    // [64][SR64]
    float* SA  = sm + B64;
    float* SB  = SA + B64;              // K^T [128][SKT64] OR normal [64][SR64]
    float* SC  = SB + KT64;
    float* SCR = SC + B64;              // [256]

    int tid  = threadIdx.x;
    int w    = tid >> 5;
    int lane = tid & 31;
    int nlong = g_longcount;

    for (int i = blockIdx.x; i < nlong; i += gridDim.x) {
        int g     = g_longlist[i];
        int start = g_starts[g];
        int cnt   = g_starts[g + 1] - start;
        int len   = cnt < 64 ? cnt : 64;
        int lenr  = (len + 7) & ~7;
        if (lenr > 64) lenr = 64;

        for (int r = w; r < lenr; r += 8) {
            if (r < len) {
                int rx = rxn_idx[start + r];
                ((float4*)(Sst + r * SR64))[lane] = ((const float4*)(rf + (size_t)rx * CC))[lane];
            } else {
                ((float4*)(Sst + r * SR64))[lane] = make_float4(0.f, 0.f, 0.f, 0.f);
            }
        }
        __syncthreads();

        for (int blk = 0; blk < 2; blk++) {
            const float* wq = Wq + blk * CC * CC;  const float* wk = Wk + blk * CC * CC;
            const float* wv = Wv + blk * CC * CC;  const float* wo = Wo + blk * CC * CC;
            const float* wl = Wlin + blk * CC * CC;
            mm64row<false, false>(Sst, wq, bq + blk * CC, SA, lenr, w, lane);
            mm64row<true,  false>(Sst, wk, bk + blk * CC, SB, lenr, w, lane);
            mm64row<false, false>(Sst, wv, bv + blk * CC, SC, lenr, w, lane);
            __syncthreads();
            attn64(SA, SB, SC, lenr, len, lenr, w, lane);
            __syncthreads();
            mm64row<false, false>(SA, wo, bo + blk * CC, SB, lenr, w, lane);
            __syncthreads();
            lnres<SR64>(SB, Sst, Sst, lenr, len, g1 + blk * CC, b1 + blk * CC, w, lane);
            __syncthreads();
            mm64row<false, true>(Sst, wl, blin + blk * CC, SC, lenr, w, lane);
            __syncthreads();
            lnres<SR64>(SC, Sst, Sst, lenr, lenr, g2 + blk * CC, b2 + blk * CC, w, lane);
            __syncthreads();
        }
        {
            const int blk = 2;
            mm1_part(seed, Wq + blk * CC * CC, SCR, tid);
            mm64row<true,  false>(Sst, Wk + blk * CC * CC, bk + blk * CC, SB, lenr, w, lane);
            mm64row<false, false>(Sst, Wv + blk * CC * CC, bv + blk * CC, SC, lenr, w, lane);
            __syncthreads();
            mm1_fin<false>(SCR, bq + blk * CC, SA, tid);
            __syncthreads();
            attn64(SA, SB, SC, 1, len, lenr, w, lane);
            __syncthreads();
            mm1_part(SA, Wo + blk * CC * CC, SCR, tid);
            __syncthreads();
            mm1_fin<false>(SCR, bo + blk * CC, SB, tid);
            __syncthreads();
            lnres<SR64>(SB, seed, Sst, 1, 1, g1 + blk * CC, b1 + blk * CC, w, lane);
            __syncthreads();
            mm1_part(Sst, Wlin + blk * CC * CC, SCR, tid);
            __syncthreads();
            mm1_fin<true>(SCR, blin + blk * CC, SC, tid);
            __syncthreads();
            lnres<SR64>(SC, Sst, Sst, 1, 1, g2 + blk * CC, b2 + blk * CC, w, lane);
            __syncthreads();
        }
        {
            const int blk = 3;
            mm1_part(Sst, Wv + blk * CC * CC, SCR, tid);
            __syncthreads();
            mm1_fin<false>(SCR, bv + blk * CC, SA, tid);
            __syncthreads();
            mm1_part(SA, Wo + blk * CC * CC, SCR, tid);
            __syncthreads();
            mm1_fin<false>(SCR, bo + blk * CC, SB, tid);
            __syncthreads();
            lnres<SR64>(SB, Sst, Sst, 1, 1, g1 + blk * CC, b1 + blk * CC, w, lane);
            __syncthreads();
            mm1_part(Sst, Wlin + blk * CC * CC, SCR, tid);
            __syncthreads();
            mm1_fin<true>(SCR, blin + blk * CC, SC, tid);
            __syncthreads();
            lnres<SR64>(SC, Sst, Sst, 1, 1, g2 + blk * CC, b2 + blk * CC, w, lane);
            __syncthreads();

            if (tid < CC) {
                float v = Sst[tid];
                if (v != v) v = 0.f;
                v = fminf(fmaxf(v, -3.402823466e38f), 3.402823466e38f);
                out[(size_t)g * CC + tid] = v;
            }
        }
        __syncthreads();    // Sst reused next iteration
    }
}

extern "C" void kernel_launch(void* const* d_in, const int* in_sizes, int n_in,
                              void* d_out, int out_size)
{
    const float* rf   = (const float*)d_in[0];
    const float* Wq   = (const float*)d_in[1];
    const float* Wk   = (const float*)d_in[2];
    const float* Wv   = (const float*)d_in[3];
    const float* Wo   = (const float*)d_in[4];
    const float* bq   = (const float*)d_in[5];
    const float* bk   = (const float*)d_in[6];
    const float* bv   = (const float*)d_in[7];
    const float* bo   = (const float*)d_in[8];
    const float* Wlin = (const float*)d_in[9];
    const float* blin = (const float*)d_in[10];
    const float* g1   = (const float*)d_in[11];
    const float* b1   = (const float*)d_in[12];
    const float* g2   = (const float*)d_in[13];
    const float* b2   = (const float*)d_in[14];
    const float* seed = (const float*)d_in[15];
    const int*   rxn  = (const int*)d_in[16];
    const int*   gidx = (const int*)d_in[17];
    int E = in_sizes[16];

    cudaFuncSetAttribute(gene_main32, cudaFuncAttributeMaxDynamicSharedMemorySize, SM32_BYTES);
    cudaFuncSetAttribute(gene_long64, cudaFuncAttributeMaxDynamicSharedMemorySize, SM64_BYTES);

    seg_bounds_kernel<<<(E + 255) / 256, 256>>>(gidx, E);
    gene_main32<<<GENES, 256, SM32_BYTES>>>(rf, Wq, Wk, Wv, Wo, bq, bk, bv, bo,
                                            Wlin, blin, g1, b1, g2, b2, seed, rxn,
                                            (float*)d_out);
    gene_long64<<<128, 256, SM64_BYTES>>>(rf, Wq, Wk, Wv, Wo, bq, bk, bv, bo,
                                          Wlin, blin, g1, b1, g2, b2, seed, rxn,
                                          (float*)d_out);
}